// round 13
// baseline (speedup 1.0000x reference)
#include <cuda_runtime.h>
#include <cuda_bf16.h>
#include <cuda_fp16.h>
#include <cstdint>

#define F 128
#define MAX_ATOMS 50000
#define MAX_PAIRS 1600008
#define GEMM_GRID 148

// Scratch (device globals: no allocation allowed)
__device__ __align__(16) __half         g_xh[MAX_ATOMS * F];   // fp16 copy of x
__device__ __align__(16) __half         g_ah[MAX_PAIRS];       // fp16 copy of alpha
__device__ __align__(16) __nv_bfloat16  g_Ahi[MAX_ATOMS * F];
__device__ __align__(16) __nv_bfloat16  g_Alo[MAX_ATOMS * F];

// ---------------------------------------------------------------------------
// helpers
// ---------------------------------------------------------------------------
__device__ __forceinline__ uint32_t smem_u32(const void* p) {
    uint32_t a;
    asm("{ .reg .u64 t; cvta.to.shared.u64 t, %1; cvt.u32.u64 %0, t; }" : "=r"(a) : "l"(p));
    return a;
}
__device__ __forceinline__ void ldsm_x4(uint32_t* r, uint32_t addr) {
    asm volatile("ldmatrix.sync.aligned.m8n8.x4.shared.b16 {%0,%1,%2,%3}, [%4];"
        : "=r"(r[0]), "=r"(r[1]), "=r"(r[2]), "=r"(r[3]) : "r"(addr));
}
__device__ __forceinline__ void mma_bf16(float4& d, const uint32_t* a, const uint32_t* b) {
    asm volatile("mma.sync.aligned.m16n8k16.row.col.f32.bf16.bf16.f32 "
        "{%0,%1,%2,%3}, {%4,%5,%6,%7}, {%8,%9}, {%0,%1,%2,%3};"
        : "+f"(d.x), "+f"(d.y), "+f"(d.z), "+f"(d.w)
        : "r"(a[0]), "r"(a[1]), "r"(a[2]), "r"(a[3]), "r"(b[0]), "r"(b[1]));
}
__device__ __forceinline__ void cp_async16(uint32_t dst, const void* src, int sbytes) {
    asm volatile("cp.async.cg.shared.global [%0], [%1], 16, %2;"
                 :: "r"(dst), "l"(src), "r"(sbytes) : "memory");
}
__device__ __forceinline__ void cp_commit() {
    asm volatile("cp.async.commit_group;" ::: "memory");
}
template <int N> __device__ __forceinline__ void cp_wait() {
    asm volatile("cp.async.wait_group %0;" :: "n"(N) : "memory");
}
__device__ __forceinline__ uint32_t pack_hi2(float a, float b) {
    __nv_bfloat162 t(__float2bfloat16_rn(a), __float2bfloat16_rn(b));
    return *reinterpret_cast<uint32_t*>(&t);
}
__device__ __forceinline__ uint32_t pack_lo2(float a, float b, uint32_t hibits) {
    __nv_bfloat162 h = *reinterpret_cast<__nv_bfloat162*>(&hibits);
    __nv_bfloat162 t(__float2bfloat16_rn(a - __bfloat162float(h.x)),
                     __float2bfloat16_rn(b - __bfloat162float(h.y)));
    return *reinterpret_cast<uint32_t*>(&t);
}
__device__ __forceinline__ void sts64(uint32_t addr, uint32_t v0, uint32_t v1) {
    asm volatile("st.shared.v2.b32 [%0], {%1,%2};" :: "r"(addr), "r"(v0), "r"(v1) : "memory");
}

// mixed-precision FMA: acc(f32) += x(f16, packed pair) * a(f16 scalar)
__device__ __forceinline__ void acc_pair_h(float4& acc, uint16_t ah, uint2 u) {
    asm("{\n\t"
        ".reg .b16 x0, x1, x2, x3;\n\t"
        "mov.b32 {x0, x1}, %4;\n\t"
        "mov.b32 {x2, x3}, %5;\n\t"
        "fma.rn.f32.f16 %0, x0, %6, %0;\n\t"
        "fma.rn.f32.f16 %1, x1, %6, %1;\n\t"
        "fma.rn.f32.f16 %2, x2, %6, %2;\n\t"
        "fma.rn.f32.f16 %3, x3, %6, %3;\n\t"
        "}"
        : "+f"(acc.x), "+f"(acc.y), "+f"(acc.z), "+f"(acc.w)
        : "r"(u.x), "r"(u.y), "h"(ah));
}

// blocked SW128 atom layout offset inside a 128x128 bf16 tile (32 KB)
__device__ __forceinline__ uint32_t tile_off(int row, int col) {
    uint32_t off = (uint32_t)(((row >> 3) + ((col >> 6) << 4)) << 10)
                 + (uint32_t)((row & 7) << 7) + (uint32_t)((col & 63) << 1);
    return off ^ ((off >> 3) & 0x70);
}

// ---------------------------------------------------------------------------
// kernel 0: x fp32 -> fp16, alpha fp32 -> fp16
// ---------------------------------------------------------------------------
__global__ void x2h_kernel(const float* __restrict__ x,
                           const float* __restrict__ alpha,
                           int n8x, int n8a) {
    int stride = gridDim.x * blockDim.x;
    int gtid = blockIdx.x * blockDim.x + threadIdx.x;
    const float4* s4 = (const float4*)x;
    uint4* d = (uint4*)g_xh;
    for (int i = gtid; i < n8x; i += stride) {
        float4 v0 = s4[2 * i];
        float4 v1 = s4[2 * i + 1];
        __half2 h0 = __floats2half2_rn(v0.x, v0.y);
        __half2 h1 = __floats2half2_rn(v0.z, v0.w);
        __half2 h2 = __floats2half2_rn(v1.x, v1.y);
        __half2 h3 = __floats2half2_rn(v1.z, v1.w);
        d[i] = uint4{*reinterpret_cast<uint32_t*>(&h0), *reinterpret_cast<uint32_t*>(&h1),
                     *reinterpret_cast<uint32_t*>(&h2), *reinterpret_cast<uint32_t*>(&h3)};
    }
    const float4* a4 = (const float4*)alpha;
    uint4* da = (uint4*)g_ah;
    for (int i = gtid; i < n8a; i += stride) {
        float4 v0 = a4[2 * i];
        float4 v1 = a4[2 * i + 1];
        __half2 h0 = __floats2half2_rn(v0.x, v0.y);
        __half2 h1 = __floats2half2_rn(v0.z, v0.w);
        __half2 h2 = __floats2half2_rn(v1.x, v1.y);
        __half2 h3 = __floats2half2_rn(v1.z, v1.w);
        da[i] = uint4{*reinterpret_cast<uint32_t*>(&h0), *reinterpret_cast<uint32_t*>(&h1),
                      *reinterpret_cast<uint32_t*>(&h2), *reinterpret_cast<uint32_t*>(&h3)};
    }
}

// scalar tail for alpha conversion (n_pairs % 8)
__global__ void a2h_tail_kernel(const float* __restrict__ alpha, int start, int n) {
    int i = start + threadIdx.x;
    if (i < n) g_ah[i] = __float2half_rn(alpha[i]);
}

// ---------------------------------------------------------------------------
// kernel 1: per-atom scatter on [atom_base, atom_lim).
// fp16 gather + fp16 alpha + mixed fma.rn.f32.f16 accumulation (no converts).
// ---------------------------------------------------------------------------
__global__ void __launch_bounds__(256)
scatter_atom_kernel(const int* __restrict__ idx_i,
                    const int* __restrict__ idx_j,
                    int n_pairs, int atom_base, int atom_lim) {
    __shared__ int s_b[9];
    int tid = threadIdx.x;
    int atom0 = atom_base + blockIdx.x * 8;

    if (tid < 9) {
        int v = atom0 + tid;
        int lo = 0, hi = n_pairs;
        while (lo < hi) {
            int mid = (lo + hi) >> 1;
            if (__ldg(idx_i + mid) < v) lo = mid + 1; else hi = mid;
        }
        s_b[tid] = lo;
    }
    __syncthreads();

    int warp = tid >> 5;
    int lane = tid & 31;
    int atom = atom0 + warp;
    if (atom >= atom_lim) return;

    int lo = s_b[warp];
    int hi = s_b[warp + 1];

    const uint2* xh = (const uint2*)g_xh;   // 32 x uint2 per row (256B)
    const __half* ah = g_ah;
    float4 acc = {0.f, 0.f, 0.f, 0.f};

    int p = lo;
    // scalar head to 8-pair (16B idx / 16B alpha-h) alignment
    for (; p < hi && (p & 7); p++) {
        int j0 = __ldg(idx_j + p);
        uint16_t a0 = __half_as_ushort(__ldg(ah + p));
        acc_pair_h(acc, a0, __ldg(xh + (size_t)j0 * 32 + lane));
    }
    // main loop: 8 pairs = 2x int4 idx + 1x uint4 alpha halves + 8 gathers
    for (; p + 8 <= hi; p += 8) {
        int4  j0 = __ldg((const int4*)(idx_j + p));
        int4  j1 = __ldg((const int4*)(idx_j + p + 4));
        uint4 ap = __ldg((const uint4*)(ah + p));   // 8 fp16 alphas
        uint2 v0 = __ldg(xh + (size_t)j0.x * 32 + lane);
        uint2 v1 = __ldg(xh + (size_t)j0.y * 32 + lane);
        uint2 v2 = __ldg(xh + (size_t)j0.z * 32 + lane);
        uint2 v3 = __ldg(xh + (size_t)j0.w * 32 + lane);
        uint2 v4 = __ldg(xh + (size_t)j1.x * 32 + lane);
        uint2 v5 = __ldg(xh + (size_t)j1.y * 32 + lane);
        uint2 v6 = __ldg(xh + (size_t)j1.z * 32 + lane);
        uint2 v7 = __ldg(xh + (size_t)j1.w * 32 + lane);
        acc_pair_h(acc, (uint16_t)(ap.x & 0xFFFFu), v0);
        acc_pair_h(acc, (uint16_t)(ap.x >> 16),     v1);
        acc_pair_h(acc, (uint16_t)(ap.y & 0xFFFFu), v2);
        acc_pair_h(acc, (uint16_t)(ap.y >> 16),     v3);
        acc_pair_h(acc, (uint16_t)(ap.z & 0xFFFFu), v4);
        acc_pair_h(acc, (uint16_t)(ap.z >> 16),     v5);
        acc_pair_h(acc, (uint16_t)(ap.w & 0xFFFFu), v6);
        acc_pair_h(acc, (uint16_t)(ap.w >> 16),     v7);
    }
    // scalar tail
    for (; p < hi; p++) {
        int j0 = __ldg(idx_j + p);
        uint16_t a0 = __half_as_ushort(__ldg(ah + p));
        acc_pair_h(acc, a0, __ldg(xh + (size_t)j0 * 32 + lane));
    }

    // fused fp32 -> bf16 hi/lo conversion + packed stores
    uint32_t h0 = pack_hi2(acc.x, acc.y);
    uint32_t h1 = pack_hi2(acc.z, acc.w);
    uint32_t l0 = pack_lo2(acc.x, acc.y, h0);
    uint32_t l1 = pack_lo2(acc.z, acc.w, h1);
    *(uint2*)(g_Ahi + (size_t)atom * F + lane * 4) = uint2{h0, h1};
    *(uint2*)(g_Alo + (size_t)atom * F + lane * 4) = uint2{l0, l1};
}

// ---------------------------------------------------------------------------
// kernel 2: persistent HMMA GEMM  Y[M,128] = A @ W^T  (3x bf16 hi/lo passes)
// W converted fp32->bf16 hi/lo in-prologue. A tiles double-buffered (cp.async).
// (unchanged, passing since R9)
// ---------------------------------------------------------------------------
__device__ __forceinline__ void load_Atile(uint32_t dstbase, int m0, int M, int tid) {
    #pragma unroll
    for (int it = 0; it < 16; it++) {
        int idx   = tid + (it << 8);
        int which = idx >> 11;              // 0 = hi, 1 = lo
        int e     = idx & 2047;
        int row   = e >> 4;
        int col   = (e & 15) << 3;
        int gm    = m0 + row;
        const __nv_bfloat16* src =
            ((which ? g_Alo : g_Ahi) + (size_t)(gm < M ? gm : 0) * F + col);
        cp_async16(dstbase + (which << 15) + tile_off(row, col), src, (gm < M) ? 16 : 0);
    }
}

__global__ void __launch_bounds__(256, 1)
gemm_kernel(const float* __restrict__ W, float* __restrict__ Y, int M, int ntiles) {
    extern __shared__ char dyn_smem[];
    uint32_t base = (smem_u32(dyn_smem) + 1023u) & ~1023u;
    // layout: Whi @0, Wlo @32K, buf0(hi@64K, lo@96K), buf1(hi@128K, lo@160K)

    int tid  = threadIdx.x;
    int wid  = tid >> 5;
    int lane = tid & 31;

    // prologue: W fp32 -> bf16 hi/lo straight into SMEM (SW128 layout)
    for (int idx = tid; idx < 2048; idx += 256) {
        int row = idx >> 4;
        int c8  = (idx & 15) << 3;
        const float4* wp = (const float4*)(W + row * F + c8);
        float4 v0 = __ldg(wp);
        float4 v1 = __ldg(wp + 1);
        uint32_t h0 = pack_hi2(v0.x, v0.y), h1 = pack_hi2(v0.z, v0.w);
        uint32_t h2 = pack_hi2(v1.x, v1.y), h3 = pack_hi2(v1.z, v1.w);
        uint32_t l0 = pack_lo2(v0.x, v0.y, h0), l1 = pack_lo2(v0.z, v0.w, h1);
        uint32_t l2 = pack_lo2(v1.x, v1.y, h2), l3 = pack_lo2(v1.z, v1.w, h3);
        uint32_t o = tile_off(row, c8);
        sts64(base + o,          h0, h1); sts64(base + o + 8,          h2, h3);
        sts64(base + 32768u + o, l0, l1); sts64(base + 32768u + o + 8, l2, l3);
    }

    int t0 = blockIdx.x;
    if (t0 < ntiles) load_Atile(base + (2u << 15), t0 << 7, M, tid);
    cp_commit();

    int warp_m = wid >> 2;
    int warp_n = wid & 3;
    int mrowA  = warp_m * 64 + (lane & 15);
    int kcolA  = (lane >> 4) << 3;
    int nrowB  = warp_n * 32 + ((lane >> 4) << 3) + (lane & 7);
    int kcolB  = ((lane >> 3) & 1) << 3;

    int parity = 0;
    for (int t = t0; t < ntiles; t += GEMM_GRID) {
        int  nt        = t + GEMM_GRID;
        bool have_next = nt < ntiles;
        if (have_next) {
            load_Atile(base + (2u << 15) + (uint32_t)((parity ^ 1) << 16), nt << 7, M, tid);
            cp_commit();
            cp_wait<1>();
        } else {
            cp_wait<0>();
        }
        __syncthreads();

        uint32_t Abase = base + (2u << 15) + (uint32_t)(parity << 16);
        int m0 = t << 7;

        float4 acc[4][4];
        #pragma unroll
        for (int i = 0; i < 4; i++)
            #pragma unroll
            for (int j = 0; j < 4; j++)
                acc[i][j] = float4{0.f, 0.f, 0.f, 0.f};

        #pragma unroll 1
        for (int kk = 0; kk < 24; kk++) {
            int p  = kk >> 3;
            int k0 = (kk & 7) << 4;
            uint32_t smA = Abase + ((p == 2) ? (1u << 15) : 0u);   // hi,hi,lo
            uint32_t smW = base  + ((p == 1) ? (1u << 15) : 0u);   // hi,lo,hi

            uint32_t afr[4][4];
            #pragma unroll
            for (int mf = 0; mf < 4; mf++)
                ldsm_x4(afr[mf], smA + tile_off(mrowA + mf * 16, k0 + kcolA));

            uint32_t bq[2][4];
            ldsm_x4(bq[0], smW + tile_off(nrowB,      k0 + kcolB));
            ldsm_x4(bq[1], smW + tile_off(nrowB + 16, k0 + kcolB));

            #pragma unroll
            for (int mf = 0; mf < 4; mf++) {
                mma_bf16(acc[mf][0], afr[mf], &bq[0][0]);
                mma_bf16(acc[mf][1], afr[mf], &bq[0][2]);
                mma_bf16(acc[mf][2], afr[mf], &bq[1][0]);
                mma_bf16(acc[mf][3], afr[mf], &bq[1][2]);
            }
        }

        int rbase = m0 + warp_m * 64 + (lane >> 2);
        int cbase = warp_n * 32 + ((lane & 3) << 1);
        #pragma unroll
        for (int mf = 0; mf < 4; mf++) {
            int r0 = rbase + mf * 16;
            #pragma unroll
            for (int nf = 0; nf < 4; nf++) {
                int c = cbase + nf * 8;
                if (r0 < M)
                    *(float2*)(Y + (size_t)r0 * F + c) = float2{acc[mf][nf].x, acc[mf][nf].y};
                if (r0 + 8 < M)
                    *(float2*)(Y + (size_t)(r0 + 8) * F + c) = float2{acc[mf][nf].z, acc[mf][nf].w};
            }
        }
        __syncthreads();
        parity ^= 1;
    }
}

// ---------------------------------------------------------------------------
// launcher
// ---------------------------------------------------------------------------
extern "C" void kernel_launch(void* const* d_in, const int* in_sizes, int n_in,
                              void* d_out, int out_size) {
    const float* x     = (const float*)d_in[0];
    const float* alpha = (const float*)d_in[1];
    const int*   idx_i = (const int*)d_in[2];
    const int*   idx_j = (const int*)d_in[3];
    const float* W     = (const float*)d_in[4];
    float*       Y     = (float*)d_out;

    int n_atoms = in_sizes[0] / F;
    int n_pairs = in_sizes[1];
    int ntiles  = (n_atoms + 127) / 128;

    // 0: x -> fp16, alpha -> fp16
    int n8a = n_pairs / 8;
    x2h_kernel<<<1024, 256>>>(x, alpha, n_atoms * 16, n8a);
    if (n_pairs & 7)
        a2h_tail_kernel<<<1, 8>>>(alpha, n8a * 8, n_pairs);

    // 1: per-atom scatter in two halves (diagnostic split, ~free)
    int half = ((n_atoms / 2) + 7) & ~7;
    scatter_atom_kernel<<<(half + 7) / 8, 256>>>(idx_i, idx_j, n_pairs, 0, half);
    scatter_atom_kernel<<<(n_atoms - half + 7) / 8, 256>>>(idx_i, idx_j, n_pairs, half, n_atoms);

    // 2: persistent pipelined HMMA GEMM (W converted in-prologue)
    cudaFuncSetAttribute(gemm_kernel, cudaFuncAttributeMaxDynamicSharedMemorySize, 196608);
    gemm_kernel<<<GEMM_GRID, 256, 196608>>>(W, Y, n_atoms, ntiles);
}

// round 14
// speedup vs baseline: 1.3366x; 1.3366x over previous
#include <cuda_runtime.h>
#include <cuda_bf16.h>
#include <cuda_fp16.h>
#include <cstdint>

#define F 128
#define MAX_ATOMS 50000
#define GEMM_GRID 296   // 2 CTAs/SM (96KB smem each)

// Scratch (device globals: no allocation allowed)
__device__ __align__(16) __half g_xh[MAX_ATOMS * F];   // fp16 copy of x
__device__ __align__(16) __half g_Ah[MAX_ATOMS * F];   // fp16 scatter result

// ---------------------------------------------------------------------------
// helpers
// ---------------------------------------------------------------------------
__device__ __forceinline__ uint32_t smem_u32(const void* p) {
    uint32_t a;
    asm("{ .reg .u64 t; cvta.to.shared.u64 t, %1; cvt.u32.u64 %0, t; }" : "=r"(a) : "l"(p));
    return a;
}
__device__ __forceinline__ void ldsm_x4(uint32_t* r, uint32_t addr) {
    asm volatile("ldmatrix.sync.aligned.m8n8.x4.shared.b16 {%0,%1,%2,%3}, [%4];"
        : "=r"(r[0]), "=r"(r[1]), "=r"(r[2]), "=r"(r[3]) : "r"(addr));
}
__device__ __forceinline__ void mma_f16(float4& d, const uint32_t* a, const uint32_t* b) {
    asm volatile("mma.sync.aligned.m16n8k16.row.col.f32.f16.f16.f32 "
        "{%0,%1,%2,%3}, {%4,%5,%6,%7}, {%8,%9}, {%0,%1,%2,%3};"
        : "+f"(d.x), "+f"(d.y), "+f"(d.z), "+f"(d.w)
        : "r"(a[0]), "r"(a[1]), "r"(a[2]), "r"(a[3]), "r"(b[0]), "r"(b[1]));
}
__device__ __forceinline__ void cp_async16(uint32_t dst, const void* src, int sbytes) {
    asm volatile("cp.async.cg.shared.global [%0], [%1], 16, %2;"
                 :: "r"(dst), "l"(src), "r"(sbytes) : "memory");
}
__device__ __forceinline__ void cp_commit() {
    asm volatile("cp.async.commit_group;" ::: "memory");
}
template <int N> __device__ __forceinline__ void cp_wait() {
    asm volatile("cp.async.wait_group %0;" :: "n"(N) : "memory");
}
__device__ __forceinline__ void sts64(uint32_t addr, uint32_t v0, uint32_t v1) {
    asm volatile("st.shared.v2.b32 [%0], {%1,%2};" :: "r"(addr), "r"(v0), "r"(v1) : "memory");
}

// blocked SW128 atom layout offset inside a 128x128 fp16 tile (32 KB)
__device__ __forceinline__ uint32_t tile_off(int row, int col) {
    uint32_t off = (uint32_t)(((row >> 3) + ((col >> 6) << 4)) << 10)
                 + (uint32_t)((row & 7) << 7) + (uint32_t)((col & 63) << 1);
    return off ^ ((off >> 3) & 0x70);
}

// ---------------------------------------------------------------------------
// kernel 0: x fp32 -> fp16 (8 floats / thread, 16B stores)
// ---------------------------------------------------------------------------
__global__ void x2h_kernel(const float* __restrict__ x, int n8) {
    int stride = gridDim.x * blockDim.x;
    const float4* s4 = (const float4*)x;
    uint4* d = (uint4*)g_xh;
    for (int i = blockIdx.x * blockDim.x + threadIdx.x; i < n8; i += stride) {
        float4 v0 = s4[2 * i];
        float4 v1 = s4[2 * i + 1];
        __half2 h0 = __floats2half2_rn(v0.x, v0.y);
        __half2 h1 = __floats2half2_rn(v0.z, v0.w);
        __half2 h2 = __floats2half2_rn(v1.x, v1.y);
        __half2 h3 = __floats2half2_rn(v1.z, v1.w);
        d[i] = uint4{*reinterpret_cast<uint32_t*>(&h0), *reinterpret_cast<uint32_t*>(&h1),
                     *reinterpret_cast<uint32_t*>(&h2), *reinterpret_cast<uint32_t*>(&h3)};
    }
}

// ---------------------------------------------------------------------------
// kernel 1: per-atom scatter (exact R12 inner loop), fp16 A output.
// ---------------------------------------------------------------------------
__device__ __forceinline__ void acc_pair(float4& acc, float a, uint2 u) {
    float2 f0 = __half22float2(*reinterpret_cast<__half2*>(&u.x));
    float2 f1 = __half22float2(*reinterpret_cast<__half2*>(&u.y));
    acc.x = fmaf(a, f0.x, acc.x);
    acc.y = fmaf(a, f0.y, acc.y);
    acc.z = fmaf(a, f1.x, acc.z);
    acc.w = fmaf(a, f1.y, acc.w);
}

__global__ void __launch_bounds__(256)
scatter_atom_kernel(const float* __restrict__ alpha,
                    const int* __restrict__ idx_i,
                    const int* __restrict__ idx_j,
                    int n_pairs, int n_atoms) {
    __shared__ int s_b[9];
    int tid = threadIdx.x;
    int atom0 = blockIdx.x * 8;

    if (tid < 9) {
        int v = atom0 + tid;
        int lo = 0, hi = n_pairs;
        while (lo < hi) {
            int mid = (lo + hi) >> 1;
            if (__ldg(idx_i + mid) < v) lo = mid + 1; else hi = mid;
        }
        s_b[tid] = lo;
    }
    __syncthreads();

    int warp = tid >> 5;
    int lane = tid & 31;
    int atom = atom0 + warp;
    if (atom >= n_atoms) return;

    int lo = s_b[warp];
    int hi = s_b[warp + 1];

    const uint2* xh = (const uint2*)g_xh;   // 32 x uint2 per row (256B)
    float4 acc = {0.f, 0.f, 0.f, 0.f};

    int p = lo;
    for (; p < hi && (p & 3); p++) {
        int   j0 = __ldg(idx_j + p);
        float a0 = __ldg(alpha + p);
        acc_pair(acc, a0, __ldg(xh + (size_t)j0 * 32 + lane));
    }
    for (; p + 8 <= hi; p += 8) {
        int4   j0 = __ldg((const int4*)(idx_j + p));
        int4   j1 = __ldg((const int4*)(idx_j + p + 4));
        float4 a0 = __ldg((const float4*)(alpha + p));
        float4 a1 = __ldg((const float4*)(alpha + p + 4));
        uint2 v0 = __ldg(xh + (size_t)j0.x * 32 + lane);
        uint2 v1 = __ldg(xh + (size_t)j0.y * 32 + lane);
        uint2 v2 = __ldg(xh + (size_t)j0.z * 32 + lane);
        uint2 v3 = __ldg(xh + (size_t)j0.w * 32 + lane);
        uint2 v4 = __ldg(xh + (size_t)j1.x * 32 + lane);
        uint2 v5 = __ldg(xh + (size_t)j1.y * 32 + lane);
        uint2 v6 = __ldg(xh + (size_t)j1.z * 32 + lane);
        uint2 v7 = __ldg(xh + (size_t)j1.w * 32 + lane);
        acc_pair(acc, a0.x, v0);
        acc_pair(acc, a0.y, v1);
        acc_pair(acc, a0.z, v2);
        acc_pair(acc, a0.w, v3);
        acc_pair(acc, a1.x, v4);
        acc_pair(acc, a1.y, v5);
        acc_pair(acc, a1.z, v6);
        acc_pair(acc, a1.w, v7);
    }
    for (; p + 4 <= hi; p += 4) {
        int4   j0 = __ldg((const int4*)(idx_j + p));
        float4 a0 = __ldg((const float4*)(alpha + p));
        uint2 v0 = __ldg(xh + (size_t)j0.x * 32 + lane);
        uint2 v1 = __ldg(xh + (size_t)j0.y * 32 + lane);
        uint2 v2 = __ldg(xh + (size_t)j0.z * 32 + lane);
        uint2 v3 = __ldg(xh + (size_t)j0.w * 32 + lane);
        acc_pair(acc, a0.x, v0);
        acc_pair(acc, a0.y, v1);
        acc_pair(acc, a0.z, v2);
        acc_pair(acc, a0.w, v3);
    }
    for (; p < hi; p++) {
        int   j0 = __ldg(idx_j + p);
        float a0 = __ldg(alpha + p);
        acc_pair(acc, a0, __ldg(xh + (size_t)j0 * 32 + lane));
    }

    // fp16 output (single 8B store per lane)
    __half2 o0 = __floats2half2_rn(acc.x, acc.y);
    __half2 o1 = __floats2half2_rn(acc.z, acc.w);
    *(uint2*)(g_Ah + (size_t)atom * F + lane * 4) =
        uint2{*reinterpret_cast<uint32_t*>(&o0), *reinterpret_cast<uint32_t*>(&o1)};
}

// ---------------------------------------------------------------------------
// kernel 2: persistent fp16 HMMA GEMM  Y[M,128] = A @ W^T  (single pass)
// SMEM: Wh @0 (32K), A buf0 @32K, A buf1 @64K -> 96KB+pad, 2 CTAs/SM.
// ---------------------------------------------------------------------------
__device__ __forceinline__ void load_Atile(uint32_t dstbase, int m0, int M, int tid) {
    #pragma unroll
    for (int it = 0; it < 8; it++) {
        int idx = tid + (it << 8);          // 0..2047
        int row = idx >> 4;
        int col = (idx & 15) << 3;
        int gm  = m0 + row;
        const __half* src = g_Ah + (size_t)(gm < M ? gm : 0) * F + col;
        cp_async16(dstbase + tile_off(row, col), src, (gm < M) ? 16 : 0);
    }
}

__global__ void __launch_bounds__(256, 2)
gemm_kernel(const float* __restrict__ W, float* __restrict__ Y, int M, int ntiles) {
    extern __shared__ char dyn_smem[];
    uint32_t base = (smem_u32(dyn_smem) + 1023u) & ~1023u;
    // layout: Wh @0 (32K), buf0 @32K, buf1 @64K

    int tid  = threadIdx.x;
    int wid  = tid >> 5;
    int lane = tid & 31;

    // prologue: W fp32 -> fp16 straight into SMEM (SW128 layout)
    for (int idx = tid; idx < 2048; idx += 256) {
        int row = idx >> 4;
        int c8  = (idx & 15) << 3;
        const float4* wp = (const float4*)(W + row * F + c8);
        float4 v0 = __ldg(wp);
        float4 v1 = __ldg(wp + 1);
        __half2 h0 = __floats2half2_rn(v0.x, v0.y);
        __half2 h1 = __floats2half2_rn(v0.z, v0.w);
        __half2 h2 = __floats2half2_rn(v1.x, v1.y);
        __half2 h3 = __floats2half2_rn(v1.z, v1.w);
        uint32_t o = tile_off(row, c8);
        sts64(base + o,     *reinterpret_cast<uint32_t*>(&h0), *reinterpret_cast<uint32_t*>(&h1));
        sts64(base + o + 8, *reinterpret_cast<uint32_t*>(&h2), *reinterpret_cast<uint32_t*>(&h3));
    }

    int t0 = blockIdx.x;
    if (t0 < ntiles) load_Atile(base + 32768u, t0 << 7, M, tid);
    cp_commit();

    int warp_m = wid >> 2;
    int warp_n = wid & 3;
    int mrowA  = warp_m * 64 + (lane & 15);
    int kcolA  = (lane >> 4) << 3;
    int nrowB  = warp_n * 32 + ((lane >> 4) << 3) + (lane & 7);
    int kcolB  = ((lane >> 3) & 1) << 3;

    int parity = 0;
    for (int t = t0; t < ntiles; t += GEMM_GRID) {
        int  nt        = t + GEMM_GRID;
        bool have_next = nt < ntiles;
        if (have_next) {
            load_Atile(base + 32768u + (uint32_t)((parity ^ 1) << 15), nt << 7, M, tid);
            cp_commit();
            cp_wait<1>();
        } else {
            cp_wait<0>();
        }
        __syncthreads();

        uint32_t Abase = base + 32768u + (uint32_t)(parity << 15);
        int m0 = t << 7;

        float4 acc[4][4];
        #pragma unroll
        for (int i = 0; i < 4; i++)
            #pragma unroll
            for (int j = 0; j < 4; j++)
                acc[i][j] = float4{0.f, 0.f, 0.f, 0.f};

        #pragma unroll
        for (int kk = 0; kk < 8; kk++) {
            int k0 = kk << 4;

            uint32_t afr[4][4];
            #pragma unroll
            for (int mf = 0; mf < 4; mf++)
                ldsm_x4(afr[mf], Abase + tile_off(mrowA + mf * 16, k0 + kcolA));

            uint32_t bq[2][4];
            ldsm_x4(bq[0], base + tile_off(nrowB,      k0 + kcolB));
            ldsm_x4(bq[1], base + tile_off(nrowB + 16, k0 + kcolB));

            #pragma unroll
            for (int mf = 0; mf < 4; mf++) {
                mma_f16(acc[mf][0], afr[mf], &bq[0][0]);
                mma_f16(acc[mf][1], afr[mf], &bq[0][2]);
                mma_f16(acc[mf][2], afr[mf], &bq[1][0]);
                mma_f16(acc[mf][3], afr[mf], &bq[1][2]);
            }
        }

        int rbase = m0 + warp_m * 64 + (lane >> 2);
        int cbase = warp_n * 32 + ((lane & 3) << 1);
        #pragma unroll
        for (int mf = 0; mf < 4; mf++) {
            int r0 = rbase + mf * 16;
            #pragma unroll
            for (int nf = 0; nf < 4; nf++) {
                int c = cbase + nf * 8;
                if (r0 < M)
                    *(float2*)(Y + (size_t)r0 * F + c) = float2{acc[mf][nf].x, acc[mf][nf].y};
                if (r0 + 8 < M)
                    *(float2*)(Y + (size_t)(r0 + 8) * F + c) = float2{acc[mf][nf].z, acc[mf][nf].w};
            }
        }
        __syncthreads();
        parity ^= 1;
    }
}

// ---------------------------------------------------------------------------
// launcher
// ---------------------------------------------------------------------------
extern "C" void kernel_launch(void* const* d_in, const int* in_sizes, int n_in,
                              void* d_out, int out_size) {
    const float* x     = (const float*)d_in[0];
    const float* alpha = (const float*)d_in[1];
    const int*   idx_i = (const int*)d_in[2];
    const int*   idx_j = (const int*)d_in[3];
    const float* W     = (const float*)d_in[4];
    float*       Y     = (float*)d_out;

    int n_atoms = in_sizes[0] / F;
    int n_pairs = in_sizes[1];
    int ntiles  = (n_atoms + 127) / 128;

    // 0: x -> fp16
    x2h_kernel<<<1024, 256>>>(x, n_atoms * 16);

    // 1: per-atom scatter (R12 loop, fp16 output)
    int nblocks = (n_atoms + 7) / 8;
    scatter_atom_kernel<<<nblocks, 256>>>(alpha, idx_i, idx_j, n_pairs, n_atoms);

    // 2: persistent single-pass fp16 HMMA GEMM
    cudaFuncSetAttribute(gemm_kernel, cudaFuncAttributeMaxDynamicSharedMemorySize, 99328);
    int grid = (ntiles < GEMM_GRID) ? ntiles : GEMM_GRID;
    gemm_kernel<<<grid, 256, 99328>>>(W, Y, n_atoms, ntiles);
}